// round 2
// baseline (speedup 1.0000x reference)
#include <cuda_runtime.h>
#include <cstdint>

// ---------------------------------------------------------------------------
// WfcNN: fused trunk(3->128->64, tanh) + per-sample expert MLP (64->32->2)
// Strategy: counting-sort samples by expert id, pad expert segments to
// 128-sample blocks so each block is single-expert, then one fused kernel
// using fp32x2 packed FMA (fma.rn.f32x2) with all intermediates in smem.
// ---------------------------------------------------------------------------

#define BN    262144
#define NE    30
#define TILE  128
#define MAXB  (BN / TILE + NE)   // 2078: worst-case padded block count

typedef unsigned long long u64;

// scratch (static __device__ — no allocations allowed)
__device__ int g_eid[BN];
__device__ int g_sorted[BN];
__device__ int g_counts[NE];
__device__ int g_cursor[NE];
__device__ int g_blk_expert[MAXB];
__device__ int g_blk_base[MAXB];
__device__ int g_blk_n[MAXB];

// ---- fp32x2 helpers (Blackwell packed fp32) -------------------------------
__device__ __forceinline__ u64 pk(float lo, float hi) {
    u64 r; asm("mov.b64 %0,{%1,%2};" : "=l"(r) : "f"(lo), "f"(hi)); return r;
}
__device__ __forceinline__ void upk(u64 v, float& lo, float& hi) {
    asm("mov.b64 {%0,%1},%2;" : "=f"(lo), "=f"(hi) : "l"(v));
}
__device__ __forceinline__ u64 ffma2(u64 a, u64 b, u64 c) {
    u64 d; asm("fma.rn.f32x2 %0,%1,%2,%3;" : "=l"(d) : "l"(a), "l"(b), "l"(c));
    return d;
}
// tanh = 1 - 2/(exp(2x)+1): 2 MUFU + few ALU, rel err ~1e-7.
// Saturates correctly at +/-1 for |x| large (exp -> inf or 0).
__device__ __forceinline__ float tanh_fast(float x) {
    float e = __expf(2.0f * x);
    return 1.0f - __fdividef(2.0f, e + 1.0f);
}

// ---- sort prologue --------------------------------------------------------
__global__ void k_reset() {
    int t = threadIdx.x;
    if (t < NE) g_counts[t] = 0;
}

__global__ void k_hist(const int* __restrict__ n, const int* __restrict__ l,
                       const int* __restrict__ m) {
    __shared__ int sh[NE];
    int t = threadIdx.x;
    if (t < NE) sh[t] = 0;
    __syncthreads();
    int i  = blockIdx.x * 256 + t;
    int nn = n[i], ll = l[i], mm = m[i];
    // offsets = cumsum of squares: (n-1)n(2n-1)/6 -> {0,1,5,14}
    int off = (nn - 1) * nn * (2 * nn - 1) / 6;
    int eid = off + ll * ll + ll + mm;
    g_eid[i] = eid;
    atomicAdd(&sh[eid], 1);
    __syncthreads();
    if (t < NE && sh[t]) atomicAdd(&g_counts[t], sh[t]);
}

__global__ void k_scan() {
    __shared__ int soff[NE + 1], sblk[NE + 1], scnt[NE];
    int t = threadIdx.x;
    if (t == 0) {
        int off = 0, blk = 0;
        for (int e = 0; e < NE; e++) {
            int c = g_counts[e];
            scnt[e] = c; soff[e] = off; sblk[e] = blk;
            g_cursor[e] = off;
            off += c;
            blk += (c + TILE - 1) / TILE;
        }
        soff[NE] = off; sblk[NE] = blk;
    }
    __syncthreads();
    int total = sblk[NE];
    for (int b = t; b < MAXB; b += blockDim.x) {
        if (b >= total) { g_blk_expert[b] = -1; continue; }
        int e = 0;
        while (!(b >= sblk[e] && b < sblk[e + 1])) e++;
        int j = b - sblk[e];
        g_blk_expert[b] = e;
        g_blk_base[b]   = soff[e] + j * TILE;
        g_blk_n[b]      = min(TILE, scnt[e] - j * TILE);
    }
}

__global__ void k_scatter() {
    __shared__ int scnt[NE], sbase[NE];
    int t = threadIdx.x;
    if (t < NE) scnt[t] = 0;
    __syncthreads();
    int i = blockIdx.x * 256 + t;
    int e = g_eid[i];
    int r = atomicAdd(&scnt[e], 1);
    __syncthreads();
    if (t < NE) sbase[t] = scnt[t] ? atomicAdd(&g_cursor[t], scnt[t]) : 0;
    __syncthreads();
    g_sorted[sbase[e] + r] = i;
}

// ---- fused main kernel ----------------------------------------------------
// smem layout (floats):
//   sW1  [128][64]        8192
//   sH2  [64][128]        8192
//   sH1  [32][128]        4096   (reused as g[32][128] in phase B/C)
//   sWa  [64][32]         2048
//   sx   [128][4]          512   (x padded with 1.0 to fold b0)
//   sW0T [128][4]          512   (W0 transposed, col 3 = b0)
//   sb1  [64], sba[32], sWb[64], sbb[4], sidx[128 ints]
#define SMEM_FLOATS 23848
#define SMEM_BYTES  (SMEM_FLOATS * 4)

__global__ __launch_bounds__(256, 2) void k_main(
    const float* __restrict__ x,
    const float* __restrict__ W0, const float* __restrict__ b0,
    const float* __restrict__ W1, const float* __restrict__ b1,
    const float* __restrict__ Wa, const float* __restrict__ ba,
    const float* __restrict__ Wb, const float* __restrict__ bb,
    float* __restrict__ out)
{
    extern __shared__ float sm[];
    float* sW1  = sm;             // 8192
    float* sH2  = sm + 8192;      // 8192
    float* sH1  = sm + 16384;     // 4096 (union with g)
    float* sWa  = sm + 20480;     // 2048
    float* sx   = sm + 22528;     // 512
    float* sW0T = sm + 23040;     // 512
    float* sb1  = sm + 23552;     // 64
    float* sba  = sm + 23616;     // 32
    float* sWb  = sm + 23648;     // 64
    float* sbb  = sm + 23712;     // 4
    int*   sidx = (int*)(sm + 23716); // 128 ints -> ends at 23844

    const int t = threadIdx.x;
    const int b = blockIdx.x;
    const int e = g_blk_expert[b];
    if (e < 0) return;
    const int base = g_blk_base[b];
    const int nval = g_blk_n[b];

    // ---- stage weights + samples ----
    {
        const float4* W1v  = (const float4*)W1;
        float4*       sW1v = (float4*)sW1;
#pragma unroll
        for (int i = 0; i < 8; i++) sW1v[t + 256 * i] = W1v[t + 256 * i];
        const float4* Wav  = (const float4*)(Wa + e * 2048);
        float4*       sWav = (float4*)sWa;
        sWav[t]       = Wav[t];
        sWav[t + 256] = Wav[t + 256];
        if (t < 128) {
            sW0T[t * 4 + 0] = W0[t];
            sW0T[t * 4 + 1] = W0[128 + t];
            sW0T[t * 4 + 2] = W0[256 + t];
            sW0T[t * 4 + 3] = b0[t];
        }
        if (t < 64)  sb1[t] = b1[t];
        if (t < 32)  sba[t] = ba[e * 32 + t];
        if (t < 64)  sWb[t] = Wb[e * 64 + t];
        if (t < 2)   sbb[t] = bb[e * 2 + t];
        if (t < 128) {
            int pos = base + t;
            if (pos > BN - 1) pos = BN - 1;   // padded tail: compute, don't store
            int idx = g_sorted[pos];
            sidx[t] = idx;
            sx[t * 4 + 0] = x[idx * 3 + 0];
            sx[t * 4 + 1] = x[idx * 3 + 1];
            sx[t * 4 + 2] = x[idx * 3 + 2];
            sx[t * 4 + 3] = 1.0f;             // folds b0
        }
    }
    __syncthreads();

    const int og = t & 7;   // output group (8 outputs in L1, 4 in expert-a)
    const int pg = t >> 3;  // sample-pair group (4 samples)

    // ---- phase A: h2 = tanh(h1 @ W1 + b1), h1 streamed in k-chunks of 32 ----
    u64 acc[4][4];
#pragma unroll
    for (int p = 0; p < 4; p++) {
        u64 bp = pk(sb1[og * 8 + 2 * p], sb1[og * 8 + 2 * p + 1]);
#pragma unroll
        for (int s = 0; s < 4; s++) acc[s][p] = bp;
    }

    for (int kc = 0; kc < 4; kc++) {
        __syncthreads();  // protect sH1 from previous chunk's readers
        // compute h1 chunk: 32 feats x 128 samples, 16 entries/thread
#pragma unroll
        for (int i = 0; i < 16; i++) {
            int ei = t + 256 * i;
            int kk = ei >> 7, s = ei & 127;
            float4 xv = *(const float4*)(sx + s * 4);
            float4 wv = *(const float4*)(sW0T + (kc * 32 + kk) * 4);
            float pre = xv.x * wv.x + xv.y * wv.y + xv.z * wv.z + xv.w * wv.w;
            sH1[kk * 128 + s] = tanh_fast(pre);
        }
        __syncthreads();
#pragma unroll 8
        for (int kk = 0; kk < 32; kk++) {
            const int k = kc * 32 + kk;
            float4 hv = *(const float4*)(sH1 + kk * 128 + pg * 4);
            float4 w0v = *(const float4*)(sW1 + k * 64 + og * 8);
            float4 w1v = *(const float4*)(sW1 + k * 64 + og * 8 + 4);
            u64 hp[4] = { pk(hv.x, hv.x), pk(hv.y, hv.y),
                          pk(hv.z, hv.z), pk(hv.w, hv.w) };
            u64 wp[4] = { pk(w0v.x, w0v.y), pk(w0v.z, w0v.w),
                          pk(w1v.x, w1v.y), pk(w1v.z, w1v.w) };
#pragma unroll
            for (int s = 0; s < 4; s++)
#pragma unroll
                for (int p = 0; p < 4; p++)
                    acc[s][p] = ffma2(hp[s], wp[p], acc[s][p]);
        }
    }
    // epilogue A: tanh, store h2[f][sample]
#pragma unroll
    for (int s = 0; s < 4; s++)
#pragma unroll
        for (int p = 0; p < 4; p++) {
            float a0, a1; upk(acc[s][p], a0, a1);
            int f = og * 8 + 2 * p;
            sH2[f * 128 + pg * 4 + s]       = tanh_fast(a0);
            sH2[(f + 1) * 128 + pg * 4 + s] = tanh_fast(a1);
        }
    __syncthreads();

    // ---- phase B: g = tanh(h2 @ Wa[e] + ba[e]) ----
    u64 accB[4][2];
#pragma unroll
    for (int p = 0; p < 2; p++) {
        u64 bp = pk(sba[og * 4 + 2 * p], sba[og * 4 + 2 * p + 1]);
#pragma unroll
        for (int s = 0; s < 4; s++) accB[s][p] = bp;
    }
#pragma unroll 8
    for (int k = 0; k < 64; k++) {
        float4 hv = *(const float4*)(sH2 + k * 128 + pg * 4);
        float4 wv = *(const float4*)(sWa + k * 32 + og * 4);
        u64 hp[4] = { pk(hv.x, hv.x), pk(hv.y, hv.y),
                      pk(hv.z, hv.z), pk(hv.w, hv.w) };
        u64 wp[2] = { pk(wv.x, wv.y), pk(wv.z, wv.w) };
#pragma unroll
        for (int s = 0; s < 4; s++)
#pragma unroll
            for (int p = 0; p < 2; p++)
                accB[s][p] = ffma2(hp[s], wp[p], accB[s][p]);
    }
    // epilogue B: tanh, store g (reuse sH1 region)
    float* sG = sH1;
#pragma unroll
    for (int s = 0; s < 4; s++)
#pragma unroll
        for (int p = 0; p < 2; p++) {
            float a0, a1; upk(accB[s][p], a0, a1);
            int f = og * 4 + 2 * p;
            sG[f * 128 + pg * 4 + s]       = tanh_fast(a0);
            sG[(f + 1) * 128 + pg * 4 + s] = tanh_fast(a1);
        }
    __syncthreads();

    // ---- phase C: psi = g @ Wb[e] + bb[e]; normalize; scatter out ----
    if (t < 128) {
        u64 acc2 = pk(sbb[0], sbb[1]);
#pragma unroll 8
        for (int k = 0; k < 32; k++) {
            float gv = sG[k * 128 + t];
            float2 wv = *(const float2*)(sWb + 2 * k);
            acc2 = ffma2(pk(gv, gv), pk(wv.x, wv.y), acc2);
        }
        float p0, p1; upk(acc2, p0, p1);
        float r = rsqrtf(p0 * p0 + p1 * p1 + 1e-6f);
        if (t < nval) {
            int idx = sidx[t];
            out[idx * 2 + 0] = p0 * r;
            out[idx * 2 + 1] = p1 * r;
        }
    }
}

// ---------------------------------------------------------------------------
extern "C" void kernel_launch(void* const* d_in, const int* in_sizes, int n_in,
                              void* d_out, int out_size) {
    const float* x  = (const float*)d_in[0];
    const int*   n  = (const int*)d_in[1];
    const int*   l  = (const int*)d_in[2];
    const int*   m  = (const int*)d_in[3];
    const float* W0 = (const float*)d_in[4];
    const float* b0 = (const float*)d_in[5];
    const float* W1 = (const float*)d_in[6];
    const float* b1 = (const float*)d_in[7];
    const float* Wa = (const float*)d_in[8];
    const float* ba = (const float*)d_in[9];
    const float* Wb = (const float*)d_in[10];
    const float* bb = (const float*)d_in[11];
    float* out = (float*)d_out;

    cudaFuncSetAttribute(k_main, cudaFuncAttributeMaxDynamicSharedMemorySize,
                         SMEM_BYTES);

    k_reset  <<<1, 32>>>();
    k_hist   <<<BN / 256, 256>>>(n, l, m);
    k_scan   <<<1, 64>>>();
    k_scatter<<<BN / 256, 256>>>();
    k_main   <<<MAXB, 256, SMEM_BYTES>>>(x, W0, b0, W1, b1, Wa, ba, Wb, bb, out);
}

// round 4
// speedup vs baseline: 1.0123x; 1.0123x over previous
#include <cuda_runtime.h>
#include <cstdint>

// ---------------------------------------------------------------------------
// WfcNN: fused trunk(3->128->64, tanh) + per-sample expert MLP (64->32->2)
// Counting-sort by expert id -> single-expert 128-sample blocks -> fused
// kernel with fp32x2 packed FMA. Round 3: direct u64 weight loads (no pk
// movs on weights), double-buffered h1 with compute/consume overlap,
// hoisted x loads, reset folded into scan (4 launches).
// ---------------------------------------------------------------------------

#define BN    262144
#define NE    30
#define TILE  128
#define MAXB  (BN / TILE + NE)   // 2078: worst-case padded block count

typedef unsigned long long u64;

// scratch (static __device__ — no allocations allowed)
__device__ int g_eid[BN];
__device__ int g_sorted[BN];
__device__ int g_counts[NE];     // zero-initialized; k_scan re-zeroes each run
__device__ int g_cursor[NE];
__device__ int g_blk_expert[MAXB];
__device__ int g_blk_base[MAXB];
__device__ int g_blk_n[MAXB];

// ---- fp32x2 helpers (Blackwell packed fp32) -------------------------------
__device__ __forceinline__ u64 pk(float lo, float hi) {
    u64 r; asm("mov.b64 %0,{%1,%2};" : "=l"(r) : "f"(lo), "f"(hi)); return r;
}
__device__ __forceinline__ void upk(u64 v, float& lo, float& hi) {
    asm("mov.b64 {%0,%1},%2;" : "=f"(lo), "=f"(hi) : "l"(v));
}
__device__ __forceinline__ u64 ffma2(u64 a, u64 b, u64 c) {
    u64 d; asm("fma.rn.f32x2 %0,%1,%2,%3;" : "=l"(d) : "l"(a), "l"(b), "l"(c));
    return d;
}
// tanh = 1 - 2/(exp(2x)+1): 2 MUFU + few ALU, rel err ~1e-7.
__device__ __forceinline__ float tanh_fast(float x) {
    float e = __expf(2.0f * x);
    return 1.0f - __fdividef(2.0f, e + 1.0f);
}

// ---- sort prologue --------------------------------------------------------
__global__ void k_hist(const int* __restrict__ n, const int* __restrict__ l,
                       const int* __restrict__ m) {
    __shared__ int sh[NE];
    int t = threadIdx.x;
    if (t < NE) sh[t] = 0;
    __syncthreads();
    int i  = blockIdx.x * 256 + t;
    int nn = n[i], ll = l[i], mm = m[i];
    int off = (nn - 1) * nn * (2 * nn - 1) / 6;   // cumsum of squares
    int eid = off + ll * ll + ll + mm;
    g_eid[i] = eid;
    atomicAdd(&sh[eid], 1);
    __syncthreads();
    if (t < NE && sh[t]) atomicAdd(&g_counts[t], sh[t]);
}

__global__ void k_scan() {
    __shared__ int soff[NE + 1], sblk[NE + 1], scnt[NE];
    int t = threadIdx.x;
    if (t == 0) {
        int off = 0, blk = 0;
        for (int e = 0; e < NE; e++) {
            int c = g_counts[e];
            scnt[e] = c; soff[e] = off; sblk[e] = blk;
            g_cursor[e] = off;
            g_counts[e] = 0;                      // reset for next graph replay
            off += c;
            blk += (c + TILE - 1) / TILE;
        }
        soff[NE] = off; sblk[NE] = blk;
    }
    __syncthreads();
    int total = sblk[NE];
    for (int b = t; b < MAXB; b += blockDim.x) {
        if (b >= total) { g_blk_expert[b] = -1; continue; }
        int e = 0;
        while (!(b >= sblk[e] && b < sblk[e + 1])) e++;
        int j = b - sblk[e];
        g_blk_expert[b] = e;
        g_blk_base[b]   = soff[e] + j * TILE;
        g_blk_n[b]      = min(TILE, scnt[e] - j * TILE);
    }
}

__global__ void k_scatter() {
    __shared__ int scnt[NE], sbase[NE];
    int t = threadIdx.x;
    if (t < NE) scnt[t] = 0;
    __syncthreads();
    int i = blockIdx.x * 256 + t;
    int e = g_eid[i];
    int r = atomicAdd(&scnt[e], 1);
    __syncthreads();
    if (t < NE) sbase[t] = scnt[t] ? atomicAdd(&g_cursor[t], scnt[t]) : 0;
    __syncthreads();
    g_sorted[sbase[e] + r] = i;
}

// ---- fused main kernel ----------------------------------------------------
// smem layout (floats), all offsets 16-float (64B) aligned:
//   sW1   [128][64]                   0     (8192)
//   sH2   [64][128]                8192     (8192)
//   sH1   2 x [32][128]           16384     (8192, double buffer)
//   sWa   [64][32]                24576     (2048)
//   sx    [128][4]                26624     (512; x padded with 1.0)
//   sW0T  [128][4]                27136     (512; W0^T, col 3 = b0)
//   sb1   27648(64) sba 27712(32) sWb 27744(64) sbb 27808(16) sidx 27824(128)
#define SMEM_FLOATS 27952
#define SMEM_BYTES  (SMEM_FLOATS * 4)

__global__ __launch_bounds__(256, 2) void k_main(
    const float* __restrict__ x,
    const float* __restrict__ W0, const float* __restrict__ b0,
    const float* __restrict__ W1, const float* __restrict__ b1,
    const float* __restrict__ Wa, const float* __restrict__ ba,
    const float* __restrict__ Wb, const float* __restrict__ bb,
    float* __restrict__ out)
{
    extern __shared__ float sm[];
    float* sW1  = sm;
    float* sH2  = sm + 8192;
    float* sH1  = sm + 16384;         // two 4096-float buffers
    float* sWa  = sm + 24576;
    float* sx   = sm + 26624;
    float* sW0T = sm + 27136;
    float* sb1  = sm + 27648;
    float* sba  = sm + 27712;
    float* sWb  = sm + 27744;
    float* sbb  = sm + 27808;
    int*   sidx = (int*)(sm + 27824);

    const int t = threadIdx.x;
    const int b = blockIdx.x;
    const int e = g_blk_expert[b];
    if (e < 0) return;
    const int base = g_blk_base[b];
    const int nval = g_blk_n[b];

    // ---- stage weights + samples ----
    {
        const float4* W1v  = (const float4*)W1;
        float4*       sW1v = (float4*)sW1;
#pragma unroll
        for (int i = 0; i < 8; i++) sW1v[t + 256 * i] = W1v[t + 256 * i];
        const float4* Wav  = (const float4*)(Wa + e * 2048);
        float4*       sWav = (float4*)sWa;
        sWav[t]       = Wav[t];
        sWav[t + 256] = Wav[t + 256];
        if (t < 128) {
            sW0T[t * 4 + 0] = W0[t];
            sW0T[t * 4 + 1] = W0[128 + t];
            sW0T[t * 4 + 2] = W0[256 + t];
            sW0T[t * 4 + 3] = b0[t];
        }
        if (t < 64)  sb1[t] = b1[t];
        if (t < 32)  sba[t] = ba[e * 32 + t];
        if (t < 64)  sWb[t] = Wb[e * 64 + t];
        if (t < 2)   sbb[t] = bb[e * 2 + t];
        if (t < 128) {
            int pos = base + t;
            if (pos > BN - 1) pos = BN - 1;   // padded tail: compute, don't store
            int idx = g_sorted[pos];
            sidx[t] = idx;
            sx[t * 4 + 0] = x[idx * 3 + 0];
            sx[t * 4 + 1] = x[idx * 3 + 1];
            sx[t * 4 + 2] = x[idx * 3 + 2];
            sx[t * 4 + 3] = 1.0f;             // folds b0
        }
    }
    __syncthreads();

    const int og  = t & 7;    // output group: 8 outputs (4 pairs) in layer 1
    const int pg  = t >> 3;   // sample group: 4 samples
    const int pg4 = pg * 4;
    const int og8 = og * 8;

    // h1 compute: this thread's fixed sample + row, x loaded once
    const int   hs  = t & 127;
    const int   hk0 = t >> 7;
    const float4 xv = *(const float4*)(sx + hs * 4);

    // ---- phase A: h2 = tanh(h1 @ W1 + b1), double-buffered h1 chunks ----
    u64 acc[4][4];
    {
        const u64* b1p = (const u64*)sb1;
#pragma unroll
        for (int p = 0; p < 4; p++) {
            u64 bp = b1p[og * 4 + p];
#pragma unroll
            for (int s = 0; s < 4; s++) acc[s][p] = bp;
        }
    }

    // compute chunk 0 into buffer 0
#pragma unroll
    for (int i = 0; i < 16; i++) {
        int kk = hk0 + 2 * i;
        float4 wv = *(const float4*)(sW0T + kk * 4);
        float pre = fmaf(xv.x, wv.x, fmaf(xv.y, wv.y, fmaf(xv.z, wv.z, xv.w * wv.w)));
        sH1[kk * 128 + hs] = tanh_fast(pre);
    }

#pragma unroll 1
    for (int kc = 0; kc < 4; kc++) {
        __syncthreads();
        const float* cur = sH1 + (kc & 1) * 4096;
        float*       nxt = sH1 + ((kc + 1) & 1) * 4096;

        // compute next chunk (MUFU-heavy) — overlaps with consume (FMA-heavy)
        if (kc < 3) {
#pragma unroll
            for (int i = 0; i < 16; i++) {
                int kk = hk0 + 2 * i;
                float4 wv = *(const float4*)(sW0T + ((kc + 1) * 32 + kk) * 4);
                float pre = fmaf(xv.x, wv.x,
                             fmaf(xv.y, wv.y, fmaf(xv.z, wv.z, xv.w * wv.w)));
                nxt[kk * 128 + hs] = tanh_fast(pre);
            }
        }

        // consume current chunk
#pragma unroll 16
        for (int kk = 0; kk < 32; kk++) {
            const int k = kc * 32 + kk;
            float4 hv = *(const float4*)(cur + kk * 128 + pg4);
            ulonglong2 w01 = *(const ulonglong2*)(sW1 + k * 64 + og8);
            ulonglong2 w23 = *(const ulonglong2*)(sW1 + k * 64 + og8 + 4);
            u64 hp0 = pk(hv.x, hv.x), hp1 = pk(hv.y, hv.y);
            u64 hp2 = pk(hv.z, hv.z), hp3 = pk(hv.w, hv.w);
            acc[0][0] = ffma2(hp0, w01.x, acc[0][0]);
            acc[0][1] = ffma2(hp0, w01.y, acc[0][1]);
            acc[0][2] = ffma2(hp0, w23.x, acc[0][2]);
            acc[0][3] = ffma2(hp0, w23.y, acc[0][3]);
            acc[1][0] = ffma2(hp1, w01.x, acc[1][0]);
            acc[1][1] = ffma2(hp1, w01.y, acc[1][1]);
            acc[1][2] = ffma2(hp1, w23.x, acc[1][2]);
            acc[1][3] = ffma2(hp1, w23.y, acc[1][3]);
            acc[2][0] = ffma2(hp2, w01.x, acc[2][0]);
            acc[2][1] = ffma2(hp2, w01.y, acc[2][1]);
            acc[2][2] = ffma2(hp2, w23.x, acc[2][2]);
            acc[2][3] = ffma2(hp2, w23.y, acc[2][3]);
            acc[3][0] = ffma2(hp3, w01.x, acc[3][0]);
            acc[3][1] = ffma2(hp3, w01.y, acc[3][1]);
            acc[3][2] = ffma2(hp3, w23.x, acc[3][2]);
            acc[3][3] = ffma2(hp3, w23.y, acc[3][3]);
        }
    }
    // epilogue A: tanh, store h2[f][sample]
#pragma unroll
    for (int s = 0; s < 4; s++)
#pragma unroll
        for (int p = 0; p < 4; p++) {
            float a0, a1; upk(acc[s][p], a0, a1);
            int f = og8 + 2 * p;
            sH2[f * 128 + pg4 + s]       = tanh_fast(a0);
            sH2[(f + 1) * 128 + pg4 + s] = tanh_fast(a1);
        }
    __syncthreads();

    // ---- phase B: g = tanh(h2 @ Wa[e] + ba[e]) ----
    u64 accB[4][2];
    {
        const u64* bap = (const u64*)sba;
#pragma unroll
        for (int p = 0; p < 2; p++) {
            u64 bp = bap[og * 2 + p];
#pragma unroll
            for (int s = 0; s < 4; s++) accB[s][p] = bp;
        }
    }
#pragma unroll 16
    for (int k = 0; k < 64; k++) {
        float4 hv = *(const float4*)(sH2 + k * 128 + pg4);
        ulonglong2 wv = *(const ulonglong2*)(sWa + k * 32 + og * 4);
        u64 hp0 = pk(hv.x, hv.x), hp1 = pk(hv.y, hv.y);
        u64 hp2 = pk(hv.z, hv.z), hp3 = pk(hv.w, hv.w);
        accB[0][0] = ffma2(hp0, wv.x, accB[0][0]);
        accB[0][1] = ffma2(hp0, wv.y, accB[0][1]);
        accB[1][0] = ffma2(hp1, wv.x, accB[1][0]);
        accB[1][1] = ffma2(hp1, wv.y, accB[1][1]);
        accB[2][0] = ffma2(hp2, wv.x, accB[2][0]);
        accB[2][1] = ffma2(hp2, wv.y, accB[2][1]);
        accB[3][0] = ffma2(hp3, wv.x, accB[3][0]);
        accB[3][1] = ffma2(hp3, wv.y, accB[3][1]);
    }
    // epilogue B: tanh, store g (reuse sH1 region)
    float* sG = sH1;
#pragma unroll
    for (int s = 0; s < 4; s++)
#pragma unroll
        for (int p = 0; p < 2; p++) {
            float a0, a1; upk(accB[s][p], a0, a1);
            int f = og * 4 + 2 * p;
            sG[f * 128 + pg4 + s]       = tanh_fast(a0);
            sG[(f + 1) * 128 + pg4 + s] = tanh_fast(a1);
        }
    __syncthreads();

    // ---- phase C: psi = g @ Wb[e] + bb[e]; normalize; scatter out ----
    if (t < 128) {
        const u64* wbp = (const u64*)sWb;
        u64 acc2 = pk(sbb[0], sbb[1]);
#pragma unroll 8
        for (int k = 0; k < 32; k++) {
            float gv = sG[k * 128 + t];
            acc2 = ffma2(pk(gv, gv), wbp[k], acc2);
        }
        float p0, p1; upk(acc2, p0, p1);
        float r = rsqrtf(p0 * p0 + p1 * p1 + 1e-6f);
        if (t < nval) {
            int idx = sidx[t];
            out[idx * 2 + 0] = p0 * r;
            out[idx * 2 + 1] = p1 * r;
        }
    }
}

// ---------------------------------------------------------------------------
extern "C" void kernel_launch(void* const* d_in, const int* in_sizes, int n_in,
                              void* d_out, int out_size) {
    const float* x  = (const float*)d_in[0];
    const int*   n  = (const int*)d_in[1];
    const int*   l  = (const int*)d_in[2];
    const int*   m  = (const int*)d_in[3];
    const float* W0 = (const float*)d_in[4];
    const float* b0 = (const float*)d_in[5];
    const float* W1 = (const float*)d_in[6];
    const float* b1 = (const float*)d_in[7];
    const float* Wa = (const float*)d_in[8];
    const float* ba = (const float*)d_in[9];
    const float* Wb = (const float*)d_in[10];
    const float* bb = (const float*)d_in[11];
    float* out = (float*)d_out;

    cudaFuncSetAttribute(k_main, cudaFuncAttributeMaxDynamicSharedMemorySize,
                         SMEM_BYTES);

    k_hist   <<<BN / 256, 256>>>(n, l, m);
    k_scan   <<<1, 64>>>();
    k_scatter<<<BN / 256, 256>>>();
    k_main   <<<MAXB, 256, SMEM_BYTES>>>(x, W0, b0, W1, b1, Wa, ba, Wb, bb, out);
}

// round 9
// speedup vs baseline: 1.4010x; 1.3840x over previous
#include <cuda_runtime.h>
#include <cstdint>

// ---------------------------------------------------------------------------
// WfcNN via warp-level tf32 mma.sync (sm_103 baseline tensor path — tcgen05
// is 'a'-gated and rejected by this toolchain target).
// Counting-sort by expert -> single-expert 128-sample blocks ->
//   layer0: h1 = tanh(x@W0+b0) by threads -> smem [s][k] stride 132 (tf32)
//   layer1: 128x64x128 via m16n8k8 tf32 mma, +b1, tanh -> smem stride 68
//   layer2: 128x32x64 via mma, +ba, tanh -> g
//   layer3: psi = g@Wb+bb (fp32x2), L2 normalize, scatter out.
// ---------------------------------------------------------------------------

#define BN    262144
#define NE    30
#define TILE  128
#define MAXB  (BN / TILE + NE)   // 2078
#define NT    512

typedef unsigned long long u64;
typedef unsigned int       u32;

__device__ int g_eid[BN];
__device__ int g_sorted[BN];
__device__ int g_counts[NE];
__device__ int g_cursor[NE];
__device__ int g_blk_expert[MAXB];
__device__ int g_blk_base[MAXB];
__device__ int g_blk_n[MAXB];

// ---- helpers --------------------------------------------------------------
__device__ __forceinline__ float tanh_fast(float x) {
    float y; asm("tanh.approx.f32 %0, %1;" : "=f"(y) : "f"(x)); return y;
}
__device__ __forceinline__ u32 to_tf32(float f) {
    u32 r; asm("cvt.rna.tf32.f32 %0, %1;" : "=r"(r) : "f"(f)); return r;
}
__device__ __forceinline__ u64 pk(float lo, float hi) {
    u64 r; asm("mov.b64 %0,{%1,%2};" : "=l"(r) : "f"(lo), "f"(hi)); return r;
}
__device__ __forceinline__ void upk(u64 v, float& lo, float& hi) {
    asm("mov.b64 {%0,%1},%2;" : "=f"(lo), "=f"(hi) : "l"(v));
}
__device__ __forceinline__ u64 ffma2(u64 a, u64 b, u64 c) {
    u64 d; asm("fma.rn.f32x2 %0,%1,%2,%3;" : "=l"(d) : "l"(a), "l"(b), "l"(c));
    return d;
}
// m16n8k8 tf32 MMA, fp32 accumulate (baseline sm_80+ tensor path)
__device__ __forceinline__ void mma8(float* d, u32 a0, u32 a1, u32 a2, u32 a3,
                                     u32 b0, u32 b1) {
    asm volatile(
        "mma.sync.aligned.m16n8k8.row.col.f32.tf32.tf32.f32 "
        "{%0,%1,%2,%3}, {%4,%5,%6,%7}, {%8,%9}, {%0,%1,%2,%3};"
        : "+f"(d[0]), "+f"(d[1]), "+f"(d[2]), "+f"(d[3])
        : "r"(a0), "r"(a1), "r"(a2), "r"(a3), "r"(b0), "r"(b1));
}

// ---- sort prologue --------------------------------------------------------
__global__ void k_hist(const int* __restrict__ n, const int* __restrict__ l,
                       const int* __restrict__ m) {
    __shared__ int sh[NE];
    int t = threadIdx.x;
    if (t < NE) sh[t] = 0;
    __syncthreads();
    int i  = blockIdx.x * 256 + t;
    int nn = n[i], ll = l[i], mm = m[i];
    int off = (nn - 1) * nn * (2 * nn - 1) / 6;
    int eid = off + ll * ll + ll + mm;
    g_eid[i] = eid;
    atomicAdd(&sh[eid], 1);
    __syncthreads();
    if (t < NE && sh[t]) atomicAdd(&g_counts[t], sh[t]);
}

__global__ void k_scan() {
    __shared__ int soff[NE + 1], sblk[NE + 1], scnt[NE];
    int t = threadIdx.x;
    if (t == 0) {
        int off = 0, blk = 0;
        for (int e = 0; e < NE; e++) {
            int c = g_counts[e];
            scnt[e] = c; soff[e] = off; sblk[e] = blk;
            g_cursor[e] = off;
            g_counts[e] = 0;                    // reset for next graph replay
            off += c;
            blk += (c + TILE - 1) / TILE;
        }
        soff[NE] = off; sblk[NE] = blk;
    }
    __syncthreads();
    int total = sblk[NE];
    for (int b = t; b < MAXB; b += blockDim.x) {
        if (b >= total) { g_blk_expert[b] = -1; continue; }
        int e = 0;
        while (!(b >= sblk[e] && b < sblk[e + 1])) e++;
        int j = b - sblk[e];
        g_blk_expert[b] = e;
        g_blk_base[b]   = soff[e] + j * TILE;
        g_blk_n[b]      = min(TILE, scnt[e] - j * TILE);
    }
}

__global__ void k_scatter() {
    __shared__ int scnt[NE], sbase[NE];
    int t = threadIdx.x;
    if (t < NE) scnt[t] = 0;
    __syncthreads();
    int i = blockIdx.x * 256 + t;
    int e = g_eid[i];
    int r = atomicAdd(&scnt[e], 1);
    __syncthreads();
    if (t < NE) sbase[t] = scnt[t] ? atomicAdd(&g_cursor[t], scnt[t]) : 0;
    __syncthreads();
    g_sorted[sbase[e] + r] = i;
}

// ---- fused mma main kernel ------------------------------------------------
// smem (floats):
//  sA   [128][132] h1 (tf32)            0     16896  (h2 [128][68] aliases 0;
//                                                     sG [128][33] at +8704)
//  sW1  [64][132]  W1^T (tf32)      16896      8448
//  sWa  [32][68]   Wa^T (tf32)      25344      2176
//  sx   [128][4]                    27520       512
//  sW0T [128][4]                    28032       512
//  sb1 28544(64) sba 28608(32) sWb 28640(64) sbb 28704(4) sidx 28708(128)
#define OFF_A    0
#define OFF_G    8704
#define OFF_W1   16896
#define OFF_WA   25344
#define OFF_X    27520
#define OFF_W0T  28032
#define OFF_B1   28544
#define OFF_BA   28608
#define OFF_WB   28640
#define OFF_BB   28704
#define OFF_IDX  28708
#define SMEM_FLOATS 28840
#define SMEM_BYTES  (SMEM_FLOATS * 4)

__global__ __launch_bounds__(NT, 2) void k_main(
    const float* __restrict__ x,
    const float* __restrict__ W0, const float* __restrict__ b0,
    const float* __restrict__ W1, const float* __restrict__ b1,
    const float* __restrict__ Wa, const float* __restrict__ ba,
    const float* __restrict__ Wb, const float* __restrict__ bb,
    float* __restrict__ out)
{
    extern __shared__ float sm[];
    u32*   sAu  = (u32*)(sm + OFF_A);       // h1, stride 132 (tf32 bits)
    u32*   sH2u = (u32*)(sm + OFF_A);       // h2, stride 68 (alias)
    float* sG   = sm + OFF_G;               // g, stride 33
    u32*   sW1u = (u32*)(sm + OFF_W1);      // [n][k] stride 132
    u32*   sWAu = (u32*)(sm + OFF_WA);      // [n][k] stride 68
    float* sx   = sm + OFF_X;
    float* sW0T = sm + OFF_W0T;
    float* sb1  = sm + OFF_B1;
    float* sba  = sm + OFF_BA;
    float* sWb  = sm + OFF_WB;
    float* sbb  = sm + OFF_BB;
    int*   sidx = (int*)(sm + OFF_IDX);

    const int t = threadIdx.x;
    const int b = blockIdx.x;
    const int e = g_blk_expert[b];
    if (e < 0) return;
    const int base = g_blk_base[b];
    const int nval = g_blk_n[b];

    // ---- stage weights + samples (tf32-convert weights) -----------------
    {
        const float4* W1v = (const float4*)W1;         // [128k][64n]
#pragma unroll
        for (int i = 0; i < 4; i++) {
            int e4 = t + NT * i;                       // < 2048
            int k  = e4 >> 4, n4 = (e4 & 15) * 4;
            float4 v = W1v[e4];
            sW1u[(n4 + 0) * 132 + k] = to_tf32(v.x);
            sW1u[(n4 + 1) * 132 + k] = to_tf32(v.y);
            sW1u[(n4 + 2) * 132 + k] = to_tf32(v.z);
            sW1u[(n4 + 3) * 132 + k] = to_tf32(v.w);
        }
        {
            const float4* Wav = (const float4*)(Wa + e * 2048);  // [64k][32n]
            int k = t >> 3, n4 = (t & 7) * 4;
            float4 v = Wav[t];
            sWAu[(n4 + 0) * 68 + k] = to_tf32(v.x);
            sWAu[(n4 + 1) * 68 + k] = to_tf32(v.y);
            sWAu[(n4 + 2) * 68 + k] = to_tf32(v.z);
            sWAu[(n4 + 3) * 68 + k] = to_tf32(v.w);
        }
        if (t < 128) {
            sW0T[t * 4 + 0] = W0[t];
            sW0T[t * 4 + 1] = W0[128 + t];
            sW0T[t * 4 + 2] = W0[256 + t];
            sW0T[t * 4 + 3] = b0[t];
        }
        if (t < 64) sb1[t] = b1[t];
        if (t < 32) sba[t] = ba[e * 32 + t];
        if (t < 64) sWb[t] = Wb[e * 64 + t];
        if (t < 2)  sbb[t] = bb[e * 2 + t];
        if (t < 128) {
            int pos = base + t;
            if (pos > BN - 1) pos = BN - 1;   // padded tail: compute, no store
            int idx = g_sorted[pos];
            sidx[t] = idx;
            sx[t * 4 + 0] = x[idx * 3 + 0];
            sx[t * 4 + 1] = x[idx * 3 + 1];
            sx[t * 4 + 2] = x[idx * 3 + 2];
            sx[t * 4 + 3] = 1.0f;             // folds b0
        }
    }
    __syncthreads();

    // ---- layer0: h1 = tanh(x@W0+b0) -> sA[s][k], tf32 --------------------
    {
        const int s = t & 127, q = t >> 7;    // q selects 32-k chunk
        float4 xv = *(const float4*)(sx + s * 4);
#pragma unroll
        for (int i = 0; i < 8; i++) {
            uint4 hv;
            u32* hp = (u32*)&hv;
#pragma unroll
            for (int j = 0; j < 4; j++) {
                int k = q * 32 + i * 4 + j;
                float4 wv = *(const float4*)(sW0T + k * 4);  // warp-broadcast
                float pre = fmaf(xv.x, wv.x,
                             fmaf(xv.y, wv.y, fmaf(xv.z, wv.z, xv.w * wv.w)));
                hp[j] = to_tf32(tanh_fast(pre));
            }
            *(uint4*)(sAu + s * 132 + q * 32 + i * 4) = hv;
        }
    }
    __syncthreads();

    // warp tiling: 16 warps = 8 m-tiles (16 rows) x 2 n-halves
    const int w   = t >> 5, lane = t & 31;
    const int r   = lane >> 2, c = lane & 3;
    const int m0  = (w & 7) * 16;
    const int nh  = w >> 3;

    // ---- layer1 MMA: 128x64x128 -----------------------------------------
    float acc[4][4] = {};
    {
        const int nbase = nh * 32;
        const u32* pA0 = sAu + (m0 + r) * 132 + c;
        const u32* pA1 = sAu + (m0 + r + 8) * 132 + c;
#pragma unroll
        for (int kk = 0; kk < 16; kk++) {
            const int k0 = kk * 8;
            u32 a0 = pA0[k0], a2 = pA0[k0 + 4];
            u32 a1 = pA1[k0], a3 = pA1[k0 + 4];
#pragma unroll
            for (int j = 0; j < 4; j++) {
                const u32* pB = sW1u + (nbase + j * 8 + r) * 132 + k0 + c;
                mma8(acc[j], a0, a1, a2, a3, pB[0], pB[4]);
            }
        }
    }
    __syncthreads();   // all layer1 reads of sA done before h2 overwrites it

    // ---- epilogue A: h2 = tanh(D+b1) -> sH2[s][f] stride 68, tf32 --------
    {
        const int nbase = nh * 32;
#pragma unroll
        for (int j = 0; j < 4; j++) {
            int col = nbase + j * 8 + 2 * c;
            float b0v = sb1[col], b1v = sb1[col + 1];
            sH2u[(m0 + r) * 68 + col]         = to_tf32(tanh_fast(acc[j][0] + b0v));
            sH2u[(m0 + r) * 68 + col + 1]     = to_tf32(tanh_fast(acc[j][1] + b1v));
            sH2u[(m0 + r + 8) * 68 + col]     = to_tf32(tanh_fast(acc[j][2] + b0v));
            sH2u[(m0 + r + 8) * 68 + col + 1] = to_tf32(tanh_fast(acc[j][3] + b1v));
        }
    }
    __syncthreads();

    // ---- layer2 MMA: 128x32x64 ------------------------------------------
    float acc2[2][4] = {};
    {
        const int nb2 = nh * 16;
        const u32* pA0 = sH2u + (m0 + r) * 68 + c;
        const u32* pA1 = sH2u + (m0 + r + 8) * 68 + c;
#pragma unroll
        for (int kk = 0; kk < 8; kk++) {
            const int k0 = kk * 8;
            u32 a0 = pA0[k0], a2 = pA0[k0 + 4];
            u32 a1 = pA1[k0], a3 = pA1[k0 + 4];
#pragma unroll
            for (int j = 0; j < 2; j++) {
                const u32* pB = sWAu + (nb2 + j * 8 + r) * 68 + k0 + c;
                mma8(acc2[j], a0, a1, a2, a3, pB[0], pB[4]);
            }
        }
    }

    // ---- epilogue B: g = tanh(D+ba) -> sG[s][k] stride 33 (fp32) ---------
    {
        const int nb2 = nh * 16;
#pragma unroll
        for (int j = 0; j < 2; j++) {
            int col = nb2 + j * 8 + 2 * c;
            float b0v = sba[col], b1v = sba[col + 1];
            sG[(m0 + r) * 33 + col]         = tanh_fast(acc2[j][0] + b0v);
            sG[(m0 + r) * 33 + col + 1]     = tanh_fast(acc2[j][1] + b1v);
            sG[(m0 + r + 8) * 33 + col]     = tanh_fast(acc2[j][2] + b0v);
            sG[(m0 + r + 8) * 33 + col + 1] = tanh_fast(acc2[j][3] + b1v);
        }
    }
    __syncthreads();

    // ---- layer3: psi = g@Wb + bb; normalize; scatter out -----------------
    if (t < 128) {
        const u64* wbp = (const u64*)sWb;
        u64 acc3 = pk(sbb[0], sbb[1]);
        const float* gp = sG + t * 33;
#pragma unroll 8
        for (int k = 0; k < 32; k++) {
            float g = gp[k];
            acc3 = ffma2(pk(g, g), wbp[k], acc3);
        }
        float p0, p1; upk(acc3, p0, p1);
        float rn = rsqrtf(p0 * p0 + p1 * p1 + 1e-6f);
        if (t < nval) {
            int idx = sidx[t];
            out[idx * 2 + 0] = p0 * rn;
            out[idx * 2 + 1] = p1 * rn;
        }
    }
}

// ---------------------------------------------------------------------------
extern "C" void kernel_launch(void* const* d_in, const int* in_sizes, int n_in,
                              void* d_out, int out_size) {
    const float* x  = (const float*)d_in[0];
    const int*   n  = (const int*)d_in[1];
    const int*   l  = (const int*)d_in[2];
    const int*   m  = (const int*)d_in[3];
    const float* W0 = (const float*)d_in[4];
    const float* b0 = (const float*)d_in[5];
    const float* W1 = (const float*)d_in[6];
    const float* b1 = (const float*)d_in[7];
    const float* Wa = (const float*)d_in[8];
    const float* ba = (const float*)d_in[9];
    const float* Wb = (const float*)d_in[10];
    const float* bb = (const float*)d_in[11];
    float* out = (float*)d_out;

    cudaFuncSetAttribute(k_main, cudaFuncAttributeMaxDynamicSharedMemorySize,
                         SMEM_BYTES);

    k_hist   <<<BN / 256, 256>>>(n, l, m);
    k_scan   <<<1, 64>>>();
    k_scatter<<<BN / 256, 256>>>();
    k_main   <<<MAXB, NT, SMEM_BYTES>>>(x, W0, b0, W1, b1, Wa, ba, Wb, bb, out);
}

// round 13
// speedup vs baseline: 2.4859x; 1.7744x over previous
#include <cuda_runtime.h>
#include <cstdint>

// ---------------------------------------------------------------------------
// WfcNN via warp-level tf32 mma.sync. Round 12 = round-10 resubmit (infra
// failure last round, change never measured): XOR-swizzled [k][n] B-matrix
// layouts (conflict-free staging AND fragment reads), packed epilogue stores,
// 512-thread prologue blocks.
// ---------------------------------------------------------------------------

#define BN    262144
#define NE    30
#define TILE  128
#define MAXB  (BN / TILE + NE)   // 2078
#define NT    512

typedef unsigned long long u64;
typedef unsigned int       u32;

__device__ int g_eid[BN];
__device__ int g_sorted[BN];
__device__ int g_counts[NE];
__device__ int g_cursor[NE];
__device__ int g_blk_expert[MAXB];
__device__ int g_blk_base[MAXB];
__device__ int g_blk_n[MAXB];

// ---- helpers --------------------------------------------------------------
__device__ __forceinline__ float tanh_fast(float x) {
    float y; asm("tanh.approx.f32 %0, %1;" : "=f"(y) : "f"(x)); return y;
}
__device__ __forceinline__ u32 to_tf32(float f) {
    u32 r; asm("cvt.rna.tf32.f32 %0, %1;" : "=r"(r) : "f"(f)); return r;
}
__device__ __forceinline__ u64 pk(float lo, float hi) {
    u64 r; asm("mov.b64 %0,{%1,%2};" : "=l"(r) : "f"(lo), "f"(hi)); return r;
}
__device__ __forceinline__ void upk(u64 v, float& lo, float& hi) {
    asm("mov.b64 {%0,%1},%2;" : "=f"(lo), "=f"(hi) : "l"(v));
}
__device__ __forceinline__ u64 ffma2(u64 a, u64 b, u64 c) {
    u64 d; asm("fma.rn.f32x2 %0,%1,%2,%3;" : "=l"(d) : "l"(a), "l"(b), "l"(c));
    return d;
}
__device__ __forceinline__ void mma8(float* d, u32 a0, u32 a1, u32 a2, u32 a3,
                                     u32 b0, u32 b1) {
    asm volatile(
        "mma.sync.aligned.m16n8k8.row.col.f32.tf32.tf32.f32 "
        "{%0,%1,%2,%3}, {%4,%5,%6,%7}, {%8,%9}, {%0,%1,%2,%3};"
        : "+f"(d[0]), "+f"(d[1]), "+f"(d[2]), "+f"(d[3])
        : "r"(a0), "r"(a1), "r"(a2), "r"(a3), "r"(b0), "r"(b1));
}

// ---- sort prologue --------------------------------------------------------
__global__ void k_hist(const int* __restrict__ n, const int* __restrict__ l,
                       const int* __restrict__ m) {
    __shared__ int sh[NE];
    int t = threadIdx.x;
    if (t < NE) sh[t] = 0;
    __syncthreads();
    int i  = blockIdx.x * NT + t;
    int nn = n[i], ll = l[i], mm = m[i];
    int off = (nn - 1) * nn * (2 * nn - 1) / 6;
    int eid = off + ll * ll + ll + mm;
    g_eid[i] = eid;
    atomicAdd(&sh[eid], 1);
    __syncthreads();
    if (t < NE && sh[t]) atomicAdd(&g_counts[t], sh[t]);
}

__global__ void k_scan() {
    __shared__ int soff[NE + 1], sblk[NE + 1], scnt[NE];
    int t = threadIdx.x;
    if (t == 0) {
        int off = 0, blk = 0;
        for (int e = 0; e < NE; e++) {
            int c = g_counts[e];
            scnt[e] = c; soff[e] = off; sblk[e] = blk;
            g_cursor[e] = off;
            g_counts[e] = 0;                    // reset for next graph replay
            off += c;
            blk += (c + TILE - 1) / TILE;
        }
        soff[NE] = off; sblk[NE] = blk;
    }
    __syncthreads();
    int total = sblk[NE];
    for (int b = t; b < MAXB; b += blockDim.x) {
        if (b >= total) { g_blk_expert[b] = -1; continue; }
        int e = 0;
        while (!(b >= sblk[e] && b < sblk[e + 1])) e++;
        int j = b - sblk[e];
        g_blk_expert[b] = e;
        g_blk_base[b]   = soff[e] + j * TILE;
        g_blk_n[b]      = min(TILE, scnt[e] - j * TILE);
    }
}

__global__ void k_scatter() {
    __shared__ int scnt[NE], sbase[NE];
    int t = threadIdx.x;
    if (t < NE) scnt[t] = 0;
    __syncthreads();
    int i = blockIdx.x * NT + t;
    int e = g_eid[i];
    int r = atomicAdd(&scnt[e], 1);
    __syncthreads();
    if (t < NE) sbase[t] = scnt[t] ? atomicAdd(&g_cursor[t], scnt[t]) : 0;
    __syncthreads();
    g_sorted[sbase[e] + r] = i;
}

// ---- fused mma main kernel ------------------------------------------------
// smem (floats):
//  sA   [128][132] h1 (tf32)            0   16896  (h2 [128][68] aliases @0;
//                                                   sG [128][33] @ 8704)
//  sW1  [128][64]  W1 [k][n^swz]    16896    8192
//  sWa  [64][32]   Wa [k][n^swz]    25088    2048
//  sx   [128][4]                    27136     512
//  sW0T [128][4]                    27648     512
//  sb1 28160(64) sba 28224(32) sWb 28256(64) sbb 28320(8) sidx 28328(128)
#define OFF_A    0
#define OFF_G    8704
#define OFF_W1   16896
#define OFF_WA   25088
#define OFF_X    27136
#define OFF_W0T  27648
#define OFF_B1   28160
#define OFF_BA   28224
#define OFF_WB   28256
#define OFF_BB   28320
#define OFF_IDX  28328
#define SMEM_FLOATS 28456
#define SMEM_BYTES  (SMEM_FLOATS * 4)

__global__ __launch_bounds__(NT, 2) void k_main(
    const float* __restrict__ x,
    const float* __restrict__ W0, const float* __restrict__ b0,
    const float* __restrict__ W1, const float* __restrict__ b1,
    const float* __restrict__ Wa, const float* __restrict__ ba,
    const float* __restrict__ Wb, const float* __restrict__ bb,
    float* __restrict__ out)
{
    extern __shared__ float sm[];
    u32*   sAu  = (u32*)(sm + OFF_A);       // h1 [s][k], stride 132 (tf32)
    u32*   sH2u = (u32*)(sm + OFF_A);       // h2 [s][f], stride 68 (alias)
    float* sG   = sm + OFF_G;               // g  [s][k], stride 33
    u32*   sW1u = (u32*)(sm + OFF_W1);      // W1 [k][n ^ ((k&3)*8)]
    u32*   sWAu = (u32*)(sm + OFF_WA);      // Wa [k][n ^ ((k&3)*8)]
    float* sx   = sm + OFF_X;
    float* sW0T = sm + OFF_W0T;
    float* sb1  = sm + OFF_B1;
    float* sba  = sm + OFF_BA;
    float* sWb  = sm + OFF_WB;
    float* sbb  = sm + OFF_BB;
    int*   sidx = (int*)(sm + OFF_IDX);

    const int t = threadIdx.x;
    const int b = blockIdx.x;
    const int e = g_blk_expert[b];
    if (e < 0) return;
    const int base = g_blk_base[b];
    const int nval = g_blk_n[b];

    // ---- stage weights + samples (tf32, XOR-swizzled [k][n]) ------------
    {
        const float4* W1v = (const float4*)W1;          // [128k][64n]
#pragma unroll
        for (int i = 0; i < 4; i++) {
            int e4 = t + NT * i;                        // < 2048
            int k  = e4 >> 4, n4 = (e4 & 15) * 4;
            int f  = (k & 3) * 8;
            float4 v = W1v[e4];
            uint4  u = { to_tf32(v.x), to_tf32(v.y), to_tf32(v.z), to_tf32(v.w) };
            *(uint4*)(sW1u + k * 64 + (n4 ^ f)) = u;    // conflict-free STS.128
        }
        {
            const float4* Wav = (const float4*)(Wa + e * 2048);  // [64k][32n]
            int k = t >> 3, n4 = (t & 7) * 4;
            int f = (k & 3) * 8;
            float4 v = Wav[t];
            uint4  u = { to_tf32(v.x), to_tf32(v.y), to_tf32(v.z), to_tf32(v.w) };
            *(uint4*)(sWAu + k * 32 + (n4 ^ f)) = u;
        }
        if (t < 128) {
            sW0T[t * 4 + 0] = W0[t];
            sW0T[t * 4 + 1] = W0[128 + t];
            sW0T[t * 4 + 2] = W0[256 + t];
            sW0T[t * 4 + 3] = b0[t];
        }
        if (t < 64) sb1[t] = b1[t];
        if (t < 32) sba[t] = ba[e * 32 + t];
        if (t < 64) sWb[t] = Wb[e * 64 + t];
        if (t < 2)  sbb[t] = bb[e * 2 + t];
        if (t < 128) {
            int pos = base + t;
            if (pos > BN - 1) pos = BN - 1;   // padded tail: compute, no store
            int idx = g_sorted[pos];
            sidx[t] = idx;
            sx[t * 4 + 0] = x[idx * 3 + 0];
            sx[t * 4 + 1] = x[idx * 3 + 1];
            sx[t * 4 + 2] = x[idx * 3 + 2];
            sx[t * 4 + 3] = 1.0f;             // folds b0
        }
    }
    __syncthreads();

    // ---- layer0: h1 = tanh(x@W0+b0) -> sA[s][k], tf32 --------------------
    {
        const int s = t & 127, q = t >> 7;    // q selects 32-k chunk
        float4 xv = *(const float4*)(sx + s * 4);
#pragma unroll
        for (int i = 0; i < 8; i++) {
            uint4 hv;
            u32* hp = (u32*)&hv;
#pragma unroll
            for (int j = 0; j < 4; j++) {
                int k = q * 32 + i * 4 + j;
                float4 wv = *(const float4*)(sW0T + k * 4);  // warp-broadcast
                float pre = fmaf(xv.x, wv.x,
                             fmaf(xv.y, wv.y, fmaf(xv.z, wv.z, xv.w * wv.w)));
                hp[j] = to_tf32(tanh_fast(pre));
            }
            *(uint4*)(sAu + s * 132 + q * 32 + i * 4) = hv;
        }
    }
    __syncthreads();

    // warp tiling: 16 warps = 8 m-tiles (16 rows) x 2 n-halves
    const int w   = t >> 5, lane = t & 31;
    const int r   = lane >> 2, c = lane & 3;
    const int m0  = (w & 7) * 16;
    const int nh  = w >> 3;

    // ---- layer1 MMA: 128x64x128 -----------------------------------------
    float acc[4][4] = {};
    {
        const int nbase = nh * 32;
        const u32* pA0 = sAu + (m0 + r) * 132 + c;
        const u32* pA1 = sAu + (m0 + r + 8) * 132 + c;
        // B base: [k][n^swz]; k = k0+c (+4): (k0+c)&3 == c -> swizzle = c*8
        const u32* pB0 = sW1u + c * 64 + ((nbase + 0 * 8 + r) ^ (c * 8));
        const u32* pB1 = sW1u + c * 64 + ((nbase + 1 * 8 + r) ^ (c * 8));
        const u32* pB2 = sW1u + c * 64 + ((nbase + 2 * 8 + r) ^ (c * 8));
        const u32* pB3 = sW1u + c * 64 + ((nbase + 3 * 8 + r) ^ (c * 8));
#pragma unroll
        for (int kk = 0; kk < 16; kk++) {
            const int k0 = kk * 8;
            const int kb = k0 * 64;
            u32 a0 = pA0[k0], a2 = pA0[k0 + 4];
            u32 a1 = pA1[k0], a3 = pA1[k0 + 4];
            mma8(acc[0], a0, a1, a2, a3, pB0[kb], pB0[kb + 256]);
            mma8(acc[1], a0, a1, a2, a3, pB1[kb], pB1[kb + 256]);
            mma8(acc[2], a0, a1, a2, a3, pB2[kb], pB2[kb + 256]);
            mma8(acc[3], a0, a1, a2, a3, pB3[kb], pB3[kb + 256]);
        }
    }
    __syncthreads();   // all layer1 reads of sA done before h2 overwrites it

    // ---- epilogue A: h2 = tanh(D+b1) -> sH2[s][f] stride 68, tf32 --------
    {
        const int nbase = nh * 32;
#pragma unroll
        for (int j = 0; j < 4; j++) {
            int col = nbase + j * 8 + 2 * c;
            float b0v = sb1[col], b1v = sb1[col + 1];
            uint2 lo = { to_tf32(tanh_fast(acc[j][0] + b0v)),
                         to_tf32(tanh_fast(acc[j][1] + b1v)) };
            uint2 hi = { to_tf32(tanh_fast(acc[j][2] + b0v)),
                         to_tf32(tanh_fast(acc[j][3] + b1v)) };
            *(uint2*)(sH2u + (m0 + r) * 68 + col)     = lo;
            *(uint2*)(sH2u + (m0 + r + 8) * 68 + col) = hi;
        }
    }
    __syncthreads();

    // ---- layer2 MMA: 128x32x64 ------------------------------------------
    float acc2[2][4] = {};
    {
        const int nb2 = nh * 16;
        const u32* pA0 = sH2u + (m0 + r) * 68 + c;
        const u32* pA1 = sH2u + (m0 + r + 8) * 68 + c;
        const u32* pB0 = sWAu + c * 32 + ((nb2 + 0 * 8 + r) ^ (c * 8));
        const u32* pB1 = sWAu + c * 32 + ((nb2 + 1 * 8 + r) ^ (c * 8));
#pragma unroll
        for (int kk = 0; kk < 8; kk++) {
            const int k0 = kk * 8;
            const int kb = k0 * 32;
            u32 a0 = pA0[k0], a2 = pA0[k0 + 4];
            u32 a1 = pA1[k0], a3 = pA1[k0 + 4];
            mma8(acc2[0], a0, a1, a2, a3, pB0[kb], pB0[kb + 128]);
            mma8(acc2[1], a0, a1, a2, a3, pB1[kb], pB1[kb + 128]);
        }
    }

    // ---- epilogue B: g = tanh(D+ba) -> sG[s][k] stride 33 (fp32) ---------
    {
        const int nb2 = nh * 16;
#pragma unroll
        for (int j = 0; j < 2; j++) {
            int col = nb2 + j * 8 + 2 * c;
            float b0v = sba[col], b1v = sba[col + 1];
            sG[(m0 + r) * 33 + col]         = tanh_fast(acc2[j][0] + b0v);
            sG[(m0 + r) * 33 + col + 1]     = tanh_fast(acc2[j][1] + b1v);
            sG[(m0 + r + 8) * 33 + col]     = tanh_fast(acc2[j][2] + b0v);
            sG[(m0 + r + 8) * 33 + col + 1] = tanh_fast(acc2[j][3] + b1v);
        }
    }
    __syncthreads();

    // ---- layer3: psi = g@Wb + bb; normalize; scatter out -----------------
    if (t < 128) {
        const u64* wbp = (const u64*)sWb;
        u64 acc3 = pk(sbb[0], sbb[1]);
        const float* gp = sG + t * 33;
#pragma unroll 8
        for (int k = 0; k < 32; k++) {
            float g = gp[k];
            acc3 = ffma2(pk(g, g), wbp[k], acc3);
        }
        float p0, p1; upk(acc3, p0, p1);
        float rn = rsqrtf(p0 * p0 + p1 * p1 + 1e-6f);
        if (t < nval) {
            int idx = sidx[t];
            out[idx * 2 + 0] = p0 * rn;
            out[idx * 2 + 1] = p1 * rn;
        }
    }
}

// ---------------------------------------------------------------------------
extern "C" void kernel_launch(void* const* d_in, const int* in_sizes, int n_in,
                              void* d_out, int out_size) {
    const float* x  = (const float*)d_in[0];
    const int*   n  = (const int*)d_in[1];
    const int*   l  = (const int*)d_in[2];
    const int*   m  = (const int*)d_in[3];
    const float* W0 = (const float*)d_in[4];
    const float* b0 = (const float*)d_in[5];
    const float* W1 = (const float*)d_in[6];
    const float* b1 = (const float*)d_in[7];
    const float* Wa = (const float*)d_in[8];
    const float* ba = (const float*)d_in[9];
    const float* Wb = (const float*)d_in[10];
    const float* bb = (const float*)d_in[11];
    float* out = (float*)d_out;

    cudaFuncSetAttribute(k_main, cudaFuncAttributeMaxDynamicSharedMemorySize,
                         SMEM_BYTES);

    k_hist   <<<BN / NT, NT>>>(n, l, m);
    k_scan   <<<1, 64>>>();
    k_scatter<<<BN / NT, NT>>>();
    k_main   <<<MAXB, NT, SMEM_BYTES>>>(x, W0, b0, W1, b1, Wa, ba, Wb, bb, out);
}

// round 16
// speedup vs baseline: 3.1182x; 1.2544x over previous
#include <cuda_runtime.h>
#include <cstdint>

// ---------------------------------------------------------------------------
// WfcNN via warp-level tf32 mma.sync. Round 14: 32m x 32n warp tiles
// (layer1: 8 warps, layer2: 4 warps) to cut B-fragment re-read redundancy
// 8x -> 4x; layouts unchanged from the passing round-13 kernel.
// ---------------------------------------------------------------------------

#define BN    262144
#define NE    30
#define TILE  128
#define MAXB  (BN / TILE + NE)   // 2078
#define NT    512

typedef unsigned long long u64;
typedef unsigned int       u32;

__device__ int g_eid[BN];
__device__ int g_sorted[BN];
__device__ int g_counts[NE];
__device__ int g_cursor[NE];
__device__ int g_blk_expert[MAXB];
__device__ int g_blk_base[MAXB];
__device__ int g_blk_n[MAXB];

// ---- helpers --------------------------------------------------------------
__device__ __forceinline__ float tanh_fast(float x) {
    float y; asm("tanh.approx.f32 %0, %1;" : "=f"(y) : "f"(x)); return y;
}
__device__ __forceinline__ u32 to_tf32(float f) {
    u32 r; asm("cvt.rna.tf32.f32 %0, %1;" : "=r"(r) : "f"(f)); return r;
}
__device__ __forceinline__ u64 pk(float lo, float hi) {
    u64 r; asm("mov.b64 %0,{%1,%2};" : "=l"(r) : "f"(lo), "f"(hi)); return r;
}
__device__ __forceinline__ void upk(u64 v, float& lo, float& hi) {
    asm("mov.b64 {%0,%1},%2;" : "=f"(lo), "=f"(hi) : "l"(v));
}
__device__ __forceinline__ u64 ffma2(u64 a, u64 b, u64 c) {
    u64 d; asm("fma.rn.f32x2 %0,%1,%2,%3;" : "=l"(d) : "l"(a), "l"(b), "l"(c));
    return d;
}
__device__ __forceinline__ void mma8(float* d, u32 a0, u32 a1, u32 a2, u32 a3,
                                     u32 b0, u32 b1) {
    asm volatile(
        "mma.sync.aligned.m16n8k8.row.col.f32.tf32.tf32.f32 "
        "{%0,%1,%2,%3}, {%4,%5,%6,%7}, {%8,%9}, {%0,%1,%2,%3};"
        : "+f"(d[0]), "+f"(d[1]), "+f"(d[2]), "+f"(d[3])
        : "r"(a0), "r"(a1), "r"(a2), "r"(a3), "r"(b0), "r"(b1));
}

// ---- sort prologue --------------------------------------------------------
__global__ void k_hist(const int* __restrict__ n, const int* __restrict__ l,
                       const int* __restrict__ m) {
    __shared__ int sh[NE];
    int t = threadIdx.x;
    if (t < NE) sh[t] = 0;
    __syncthreads();
    int i  = blockIdx.x * NT + t;
    int nn = n[i], ll = l[i], mm = m[i];
    int off = (nn - 1) * nn * (2 * nn - 1) / 6;
    int eid = off + ll * ll + ll + mm;
    g_eid[i] = eid;
    atomicAdd(&sh[eid], 1);
    __syncthreads();
    if (t < NE && sh[t]) atomicAdd(&g_counts[t], sh[t]);
}

__global__ void k_scan() {
    __shared__ int soff[NE + 1], sblk[NE + 1], scnt[NE];
    int t = threadIdx.x;
    if (t == 0) {
        int off = 0, blk = 0;
        for (int e = 0; e < NE; e++) {
            int c = g_counts[e];
            scnt[e] = c; soff[e] = off; sblk[e] = blk;
            g_cursor[e] = off;
            g_counts[e] = 0;                    // reset for next graph replay
            off += c;
            blk += (c + TILE - 1) / TILE;
        }
        soff[NE] = off; sblk[NE] = blk;
    }
    __syncthreads();
    int total = sblk[NE];
    for (int b = t; b < MAXB; b += blockDim.x) {
        if (b >= total) { g_blk_expert[b] = -1; continue; }
        int e = 0;
        while (!(b >= sblk[e] && b < sblk[e + 1])) e++;
        int j = b - sblk[e];
        g_blk_expert[b] = e;
        g_blk_base[b]   = soff[e] + j * TILE;
        g_blk_n[b]      = min(TILE, scnt[e] - j * TILE);
    }
}

__global__ void k_scatter() {
    __shared__ int scnt[NE], sbase[NE];
    int t = threadIdx.x;
    if (t < NE) scnt[t] = 0;
    __syncthreads();
    int i = blockIdx.x * NT + t;
    int e = g_eid[i];
    int r = atomicAdd(&scnt[e], 1);
    __syncthreads();
    if (t < NE) sbase[t] = scnt[t] ? atomicAdd(&g_cursor[t], scnt[t]) : 0;
    __syncthreads();
    g_sorted[sbase[e] + r] = i;
}

// ---- fused mma main kernel ------------------------------------------------
// smem (floats):
//  sA   [128][132] h1 (tf32)            0   16896  (h2 [128][68] aliases @0;
//                                                   sG [128][33] @ 8704)
//  sW1  [128][64]  W1 [k][n^swz]    16896    8192
//  sWa  [64][32]   Wa [k][n^swz]    25088    2048
//  sx   [128][4]                    27136     512
//  sW0T [128][4]                    27648     512
//  sb1 28160(64) sba 28224(32) sWb 28256(64) sbb 28320(8) sidx 28328(128)
#define OFF_A    0
#define OFF_G    8704
#define OFF_W1   16896
#define OFF_WA   25088
#define OFF_X    27136
#define OFF_W0T  27648
#define OFF_B1   28160
#define OFF_BA   28224
#define OFF_WB   28256
#define OFF_BB   28320
#define OFF_IDX  28328
#define SMEM_FLOATS 28456
#define SMEM_BYTES  (SMEM_FLOATS * 4)

__global__ __launch_bounds__(NT, 2) void k_main(
    const float* __restrict__ x,
    const float* __restrict__ W0, const float* __restrict__ b0,
    const float* __restrict__ W1, const float* __restrict__ b1,
    const float* __restrict__ Wa, const float* __restrict__ ba,
    const float* __restrict__ Wb, const float* __restrict__ bb,
    float* __restrict__ out)
{
    extern __shared__ float sm[];
    u32*   sAu  = (u32*)(sm + OFF_A);       // h1 [s][k], stride 132 (tf32)
    u32*   sH2u = (u32*)(sm + OFF_A);       // h2 [s][f], stride 68 (alias)
    float* sG   = sm + OFF_G;               // g  [s][k], stride 33
    u32*   sW1u = (u32*)(sm + OFF_W1);      // W1 [k][n ^ ((k&3)*8)]
    u32*   sWAu = (u32*)(sm + OFF_WA);      // Wa [k][n ^ ((k&3)*8)]
    float* sx   = sm + OFF_X;
    float* sW0T = sm + OFF_W0T;
    float* sb1  = sm + OFF_B1;
    float* sba  = sm + OFF_BA;
    float* sWb  = sm + OFF_WB;
    float* sbb  = sm + OFF_BB;
    int*   sidx = (int*)(sm + OFF_IDX);

    const int t = threadIdx.x;
    const int b = blockIdx.x;
    const int e = g_blk_expert[b];
    if (e < 0) return;
    const int base = g_blk_base[b];
    const int nval = g_blk_n[b];

    // ---- stage weights + samples (tf32, XOR-swizzled [k][n]) ------------
    {
        const float4* W1v = (const float4*)W1;          // [128k][64n]
#pragma unroll
        for (int i = 0; i < 4; i++) {
            int e4 = t + NT * i;                        // < 2048
            int k  = e4 >> 4, n4 = (e4 & 15) * 4;
            int f  = (k & 3) * 8;
            float4 v = W1v[e4];
            uint4  u = { to_tf32(v.x), to_tf32(v.y), to_tf32(v.z), to_tf32(v.w) };
            *(uint4*)(sW1u + k * 64 + (n4 ^ f)) = u;    // conflict-free STS.128
        }
        {
            const float4* Wav = (const float4*)(Wa + e * 2048);  // [64k][32n]
            int k = t >> 3, n4 = (t & 7) * 4;
            int f = (k & 3) * 8;
            float4 v = Wav[t];
            uint4  u = { to_tf32(v.x), to_tf32(v.y), to_tf32(v.z), to_tf32(v.w) };
            *(uint4*)(sWAu + k * 32 + (n4 ^ f)) = u;
        }
        if (t < 128) {
            sW0T[t * 4 + 0] = W0[t];
            sW0T[t * 4 + 1] = W0[128 + t];
            sW0T[t * 4 + 2] = W0[256 + t];
            sW0T[t * 4 + 3] = b0[t];
        }
        if (t < 64) sb1[t] = b1[t];
        if (t < 32) sba[t] = ba[e * 32 + t];
        if (t < 64) sWb[t] = Wb[e * 64 + t];
        if (t < 2)  sbb[t] = bb[e * 2 + t];
        if (t < 128) {
            int pos = base + t;
            if (pos > BN - 1) pos = BN - 1;   // padded tail: compute, no store
            int idx = g_sorted[pos];
            sidx[t] = idx;
            sx[t * 4 + 0] = x[idx * 3 + 0];
            sx[t * 4 + 1] = x[idx * 3 + 1];
            sx[t * 4 + 2] = x[idx * 3 + 2];
            sx[t * 4 + 3] = 1.0f;             // folds b0
        }
    }
    __syncthreads();

    // ---- layer0: h1 = tanh(x@W0+b0) -> sA[s][k], tf32 --------------------
    {
        const int s = t & 127, q = t >> 7;    // q selects 32-k chunk
        float4 xv = *(const float4*)(sx + s * 4);
#pragma unroll
        for (int i = 0; i < 8; i++) {
            uint4 hv;
            u32* hp = (u32*)&hv;
#pragma unroll
            for (int j = 0; j < 4; j++) {
                int k = q * 32 + i * 4 + j;
                float4 wv = *(const float4*)(sW0T + k * 4);  // warp-broadcast
                float pre = fmaf(xv.x, wv.x,
                             fmaf(xv.y, wv.y, fmaf(xv.z, wv.z, xv.w * wv.w)));
                hp[j] = to_tf32(tanh_fast(pre));
            }
            *(uint4*)(sAu + s * 132 + q * 32 + i * 4) = hv;
        }
    }
    __syncthreads();

    const int w    = t >> 5, lane = t & 31;
    const int r    = lane >> 2, c = lane & 3;

    // ---- layer1 MMA: 128x64x128, 8 warps, 32m x 32n tiles ----------------
    // warp w<8: m0 = (w&3)*32 (2 strips of 16), nh = w>>2 (n-half)
    if (w < 8) {
        const int m0    = (w & 3) * 32;
        const int nbase = (w >> 2) * 32;
        float acc[2][4][4] = {};
        const u32* pA0 = sAu + (m0 + r) * 132 + c;          // strip 0
        const u32* pA1 = sAu + (m0 + r + 8) * 132 + c;
        const u32* pA2 = sAu + (m0 + 16 + r) * 132 + c;     // strip 1
        const u32* pA3 = sAu + (m0 + 24 + r) * 132 + c;
        // B base: [k][n^swz]; k = k0+c (+4): (k0+c)&3 == c -> swizzle = c*8
        const u32* pB0 = sW1u + c * 64 + ((nbase + 0 * 8 + r) ^ (c * 8));
        const u32* pB1 = sW1u + c * 64 + ((nbase + 1 * 8 + r) ^ (c * 8));
        const u32* pB2 = sW1u + c * 64 + ((nbase + 2 * 8 + r) ^ (c * 8));
        const u32* pB3 = sW1u + c * 64 + ((nbase + 3 * 8 + r) ^ (c * 8));
#pragma unroll
        for (int kk = 0; kk < 16; kk++) {
            const int k0 = kk * 8;
            const int kb = k0 * 64;
            u32 b00 = pB0[kb], b01 = pB0[kb + 256];
            u32 b10 = pB1[kb], b11 = pB1[kb + 256];
            u32 b20 = pB2[kb], b21 = pB2[kb + 256];
            u32 b30 = pB3[kb], b31 = pB3[kb + 256];
            {   // strip 0
                u32 a0 = pA0[k0], a2 = pA0[k0 + 4];
                u32 a1 = pA1[k0], a3 = pA1[k0 + 4];
                mma8(acc[0][0], a0, a1, a2, a3, b00, b01);
                mma8(acc[0][1], a0, a1, a2, a3, b10, b11);
                mma8(acc[0][2], a0, a1, a2, a3, b20, b21);
                mma8(acc[0][3], a0, a1, a2, a3, b30, b31);
            }
            {   // strip 1
                u32 a0 = pA2[k0], a2 = pA2[k0 + 4];
                u32 a1 = pA3[k0], a3 = pA3[k0 + 4];
                mma8(acc[1][0], a0, a1, a2, a3, b00, b01);
                mma8(acc[1][1], a0, a1, a2, a3, b10, b11);
                mma8(acc[1][2], a0, a1, a2, a3, b20, b21);
                mma8(acc[1][3], a0, a1, a2, a3, b30, b31);
            }
        }
        __syncthreads();   // all layer1 reads of sA done before h2 overwrite

        // ---- epilogue A: h2 = tanh(D+b1) -> sH2[s][f] stride 68, tf32 ----
#pragma unroll
        for (int strip = 0; strip < 2; strip++) {
            const int mr = m0 + strip * 16 + r;
#pragma unroll
            for (int j = 0; j < 4; j++) {
                int col = nbase + j * 8 + 2 * c;
                float b0v = sb1[col], b1v = sb1[col + 1];
                uint2 lo = { to_tf32(tanh_fast(acc[strip][j][0] + b0v)),
                             to_tf32(tanh_fast(acc[strip][j][1] + b1v)) };
                uint2 hi = { to_tf32(tanh_fast(acc[strip][j][2] + b0v)),
                             to_tf32(tanh_fast(acc[strip][j][3] + b1v)) };
                *(uint2*)(sH2u + mr * 68 + col)       = lo;
                *(uint2*)(sH2u + (mr + 8) * 68 + col) = hi;
            }
        }
    } else {
        __syncthreads();   // matching barrier for idle warps
    }
    __syncthreads();

    // ---- layer2 MMA: 128x32x64, 4 warps, 32m x 32n tiles -----------------
    if (w < 4) {
        const int m0 = w * 32;
        float acc2[2][4][4] = {};
        const u32* pA0 = sH2u + (m0 + r) * 68 + c;
        const u32* pA1 = sH2u + (m0 + r + 8) * 68 + c;
        const u32* pA2 = sH2u + (m0 + 16 + r) * 68 + c;
        const u32* pA3 = sH2u + (m0 + 24 + r) * 68 + c;
        const u32* pC0 = sWAu + c * 32 + ((0 * 8 + r) ^ (c * 8));
        const u32* pC1 = sWAu + c * 32 + ((1 * 8 + r) ^ (c * 8));
        const u32* pC2 = sWAu + c * 32 + ((2 * 8 + r) ^ (c * 8));
        const u32* pC3 = sWAu + c * 32 + ((3 * 8 + r) ^ (c * 8));
#pragma unroll
        for (int kk = 0; kk < 8; kk++) {
            const int k0 = kk * 8;
            const int kb = k0 * 32;
            u32 b00 = pC0[kb], b01 = pC0[kb + 128];
            u32 b10 = pC1[kb], b11 = pC1[kb + 128];
            u32 b20 = pC2[kb], b21 = pC2[kb + 128];
            u32 b30 = pC3[kb], b31 = pC3[kb + 128];
            {
                u32 a0 = pA0[k0], a2 = pA0[k0 + 4];
                u32 a1 = pA1[k0], a3 = pA1[k0 + 4];
                mma8(acc2[0][0], a0, a1, a2, a3, b00, b01);
                mma8(acc2[0][1], a0, a1, a2, a3, b10, b11);
                mma8(acc2[0][2], a0, a1, a2, a3, b20, b21);
                mma8(acc2[0][3], a0, a1, a2, a3, b30, b31);
            }
            {
                u32 a0 = pA2[k0], a2 = pA2[k0 + 4];
                u32 a1 = pA3[k0], a3 = pA3[k0 + 4];
                mma8(acc2[1][0], a0, a1, a2, a3, b00, b01);
                mma8(acc2[1][1], a0, a1, a2, a3, b10, b11);
                mma8(acc2[1][2], a0, a1, a2, a3, b20, b21);
                mma8(acc2[1][3], a0, a1, a2, a3, b30, b31);
            }
        }

        // ---- epilogue B: g = tanh(D+ba) -> sG[s][k] stride 33 (fp32) -----
#pragma unroll
        for (int strip = 0; strip < 2; strip++) {
            const int mr = m0 + strip * 16 + r;
#pragma unroll
            for (int j = 0; j < 4; j++) {
                int col = j * 8 + 2 * c;
                float b0v = sba[col], b1v = sba[col + 1];
                sG[mr * 33 + col]           = tanh_fast(acc2[strip][j][0] + b0v);
                sG[mr * 33 + col + 1]       = tanh_fast(acc2[strip][j][1] + b1v);
                sG[(mr + 8) * 33 + col]     = tanh_fast(acc2[strip][j][2] + b0v);
                sG[(mr + 8) * 33 + col + 1] = tanh_fast(acc2[strip][j][3] + b1v);
            }
        }
    }
    __syncthreads();

    // ---- layer3: psi = g@Wb + bb; normalize; scatter out -----------------
    if (t < 128) {
        const u64* wbp = (const u64*)sWb;
        u64 acc3 = pk(sbb[0], sbb[1]);
        const float* gp = sG + t * 33;
#pragma unroll 8
        for (int k = 0; k < 32; k++) {
            float g = gp[k];
            acc3 = ffma2(pk(g, g), wbp[k], acc3);
        }
        float p0, p1; upk(acc3, p0, p1);
        float rn = rsqrtf(p0 * p0 + p1 * p1 + 1e-6f);
        if (t < nval) {
            int idx = sidx[t];
            out[idx * 2 + 0] = p0 * rn;
            out[idx * 2 + 1] = p1 * rn;
        }
    }
}

// ---------------------------------------------------------------------------
extern "C" void kernel_launch(void* const* d_in, const int* in_sizes, int n_in,
                              void* d_out, int out_size) {
    const float* x  = (const float*)d_in[0];
    const int*   n  = (const int*)d_in[1];
    const int*   l  = (const int*)d_in[2];
    const int*   m  = (const int*)d_in[3];
    const float* W0 = (const float*)d_in[4];
    const float* b0 = (const float*)d_in[5];
    const float* W1 = (const float*)d_in[6];
    const float* b1 = (const float*)d_in[7];
    const float* Wa = (const float*)d_in[8];
    const float* ba = (const float*)d_in[9];
    const float* Wb = (const float*)d_in[10];
    const float* bb = (const float*)d_in[11];
    float* out = (float*)d_out;

    cudaFuncSetAttribute(k_main, cudaFuncAttributeMaxDynamicSharedMemorySize,
                         SMEM_BYTES);

    k_hist   <<<BN / NT, NT>>>(n, l, m);
    k_scan   <<<1, 256>>>();
    k_scatter<<<BN / NT, NT>>>();
    k_main   <<<MAXB, NT, SMEM_BYTES>>>(x, W0, b0, W1, b1, Wa, ba, Wb, bb, out);
}